// round 16
// baseline (speedup 1.0000x reference)
#include <cuda_runtime.h>
#include <math.h>

#define B_SAMPLES 524288
#define SBLOCKS   296
#define NWARPS    (SBLOCKS * 8)         // 2368 warps
#define CHUNKS    (B_SAMPLES / 16)      // 32768 chunks of 16 samples

// ---------------- device scratch (static, no allocation) ----------------
__device__ float gPart[SBLOCKS * 1056];       // [block][entry]
__device__ int   gTicket;                      // zero-init; self-resetting
__device__ __align__(16) float gW[64 * 120];   // fused per-j row: Wp|fiT|fsT|WAB (+pad)
__device__ float gK[64];
__device__ float gBAB[20];

// ---------------- packed f32x2 helpers ----------------
__device__ __forceinline__ float2 f2fma(float2 a, float2 b, float2 c) {
    float2 d;
    asm("fma.rn.f32x2 %0, %1, %2, %3;"
        : "=l"(reinterpret_cast<unsigned long long&>(d))
        : "l"(reinterpret_cast<const unsigned long long&>(a)),
          "l"(reinterpret_cast<const unsigned long long&>(b)),
          "l"(reinterpret_cast<const unsigned long long&>(c)));
    return d;
}
__device__ __forceinline__ float2 f2add(float2 a, float2 b) {
    float2 d;
    asm("add.rn.f32x2 %0, %1, %2;"
        : "=l"(reinterpret_cast<unsigned long long&>(d))
        : "l"(reinterpret_cast<const unsigned long long&>(a)),
          "l"(reinterpret_cast<const unsigned long long&>(b)));
    return d;
}

// exact-enough GELU: erf via Abramowitz-Stegun 7.1.26 (|eps| <= 1.5e-7 abs)
__device__ __forceinline__ float gelu_fast(float h) {
    float z  = h * 0.70710678118654752f;
    float az = fabsf(z);
    float t  = __fdividef(1.0f, fmaf(0.3275911f, az, 1.0f));
    float p  = t * fmaf(t, fmaf(t, fmaf(t, fmaf(t, 1.061405429f, -1.453152027f),
                                        1.421413741f), -0.284496736f), 0.254829592f);
    float er = 1.0f - p * __expf(-az * az);
    er = copysignf(er, z);
    return 0.5f * h * (1.0f + er);
}

// ---------------- pass 1 (fused): Gram + colsum + reduce + BN-fold/prep ----------------
__global__ void __launch_bounds__(256)
stats_prep_kernel(const float* __restrict__ x,
                  const float* __restrict__ w_in, const float* __restrict__ b_in,
                  const float* __restrict__ bn_g, const float* __restrict__ bn_b,
                  const float* __restrict__ w_fi, const float* __restrict__ w_fs,
                  const float* __restrict__ w_lc, const float* __restrict__ b_lc) {
    __shared__ float pool[8 * 1056];
    __shared__ int   sIsLast;

    const int tid  = threadIdx.x;
    const int lane = tid & 31;
    const int wid  = tid >> 5;
    const int gw   = blockIdx.x * 8 + wid;
    const int ti   = lane >> 2;
    const int tj   = lane & 3;

    float2 acc[4][4];
#pragma unroll
    for (int a = 0; a < 4; a++) {
#pragma unroll
        for (int c = 0; c < 4; c++) acc[a][c] = make_float2(0.f, 0.f);
    }
    float2 cs[4];
#pragma unroll
    for (int c = 0; c < 4; c++) cs[c] = make_float2(0.f, 0.f);

    float* stage = pool + wid * 512;

    for (int ch = gw; ch < CHUNKS; ch += NWARPS) {
        const float4* src = (const float4*)(x + (size_t)ch * 512);
        float4* dst = (float4*)stage;
#pragma unroll
        for (int k = 0; k < 4; k++)
            dst[k * 32 + lane] = src[k * 32 + lane];
        __syncwarp();

#pragma unroll 4
        for (int s = 0; s < 16; s++) {
            const float* row = stage + s * 32;
            float4 xi  = *(const float4*)(row + ti * 4);
            float4 xjA = *(const float4*)(row + tj * 8);
            float4 xjB = *(const float4*)(row + tj * 8 + 4);
            float2 xj[4];
            xj[0] = make_float2(xjA.x, xjA.y);
            xj[1] = make_float2(xjA.z, xjA.w);
            xj[2] = make_float2(xjB.x, xjB.y);
            xj[3] = make_float2(xjB.z, xjB.w);
            float xia[4] = {xi.x, xi.y, xi.z, xi.w};
#pragma unroll
            for (int a = 0; a < 4; a++) {
                float2 f = make_float2(xia[a], xia[a]);
#pragma unroll
                for (int c = 0; c < 4; c++)
                    acc[a][c] = f2fma(f, xj[c], acc[a][c]);
            }
            if (ti == 0) {
#pragma unroll
                for (int c = 0; c < 4; c++) cs[c] = f2add(cs[c], xj[c]);
            }
        }
        __syncwarp();
    }

    __syncthreads();

    float* pw = pool + wid * 1056;
#pragma unroll
    for (int a = 0; a < 4; a++) {
        int r = 4 * ti + a;
#pragma unroll
        for (int c = 0; c < 4; c++) {
            int col = 8 * tj + 2 * c;
            pw[r * 32 + col]     = acc[a][c].x;
            pw[r * 32 + col + 1] = acc[a][c].y;
        }
    }
    if (ti == 0) {
#pragma unroll
        for (int c = 0; c < 4; c++) {
            pw[1024 + 8 * tj + 2 * c]     = cs[c].x;
            pw[1024 + 8 * tj + 2 * c + 1] = cs[c].y;
        }
    }
    __syncthreads();

    for (int e = tid; e < 1056; e += 256) {
        float s = 0.0f;
#pragma unroll
        for (int w = 0; w < 8; w++) s += pool[w * 1056 + e];
        gPart[(size_t)blockIdx.x * 1056 + e] = s;
    }

    // ---- last-block finalization (deterministic: fixed summation order) ----
    __threadfence();
    __syncthreads();
    if (tid == 0) {
        int t = atomicAdd(&gTicket, 1);
        sIsLast = (t == SBLOCKS - 1) ? 1 : 0;
    }
    __syncthreads();
    if (!sIsLast) return;

    // 4 independent partial sums -> MLP=4 hides the L2 load chain
    for (int e = tid; e < 1056; e += 256) {
        float p0 = 0.f, p1 = 0.f, p2 = 0.f, p3 = 0.f;
        for (int w = 0; w < SBLOCKS; w += 4) {
            p0 += gPart[(size_t)(w    ) * 1056 + e];
            p1 += gPart[(size_t)(w + 1) * 1056 + e];
            p2 += gPart[(size_t)(w + 2) * 1056 + e];
            p3 += gPart[(size_t)(w + 3) * 1056 + e];
        }
        pool[e] = (p0 + p1) + (p2 + p3);
    }
    __syncthreads();
    if (tid == 0) gTicket = 0;   // reset for next graph replay

    const int j = tid;
    if (j < 64) {
        float w[32];
#pragma unroll
        for (int f = 0; f < 32; f++) w[f] = w_in[j * 32 + f];

        float s1 = 0.0f;
#pragma unroll
        for (int f = 0; f < 32; f++) s1 = fmaf(w[f], pool[1024 + f], s1);

        float q = 0.0f;
        for (int i = 0; i < 32; i++) {
            float t2 = 0.0f;
#pragma unroll
            for (int f = 0; f < 32; f++) t2 = fmaf(pool[i * 32 + f], w[f], t2);
            q = fmaf(w[i], t2, q);
        }

        const float invB = 1.0f / (float)B_SAMPLES;
        float bj  = b_in[j];
        float mu  = s1 * invB + bj;
        float ex2 = q * invB + 2.0f * bj * (s1 * invB) + bj * bj;
        float var = ex2 - mu * mu;
        float g   = bn_g[j] / sqrtf(var + 1e-5f);
        float k   = g * (bj - mu) + bn_b[j];

        float* row = gW + j * 120;
#pragma unroll
        for (int f = 0; f < 32; f++) row[f] = w[f] * g;
        gK[j] = k;
#pragma unroll
        for (int f = 0; f < 32; f++) {
            row[32 + f] = w_fi[f * 64 + j];
            row[64 + f] = w_fs[f * 64 + j];
        }
#pragma unroll
        for (int c = 0; c < 10; c++) {
            row[96 + c]      = w_lc[c * 64 + j]        + w_lc[(10 + c) * 64 + j];
            row[96 + 10 + c] = w_lc[(20 + c) * 64 + j] + w_lc[(30 + c) * 64 + j];
        }
        row[116] = 0.0f; row[117] = 0.0f; row[118] = 0.0f; row[119] = 0.0f;
        if (j < 10) {
            gBAB[j]      = b_lc[j]      + b_lc[10 + j];
            gBAB[10 + j] = b_lc[20 + j] + b_lc[30 + j];
        }
    }
}

// ---------------- pass 2: main fused kernel (R12 loop body, frozen) ----------------
__global__ void __launch_bounds__(128, 2)
main_kernel(const float* __restrict__ x, const float* __restrict__ b_fi,
            const float* __restrict__ b_fs, float* __restrict__ out) {
    __shared__ __align__(16) float sW[64 * 120];
    __shared__ float sK[64];
    __shared__ float sB[84];

    const int tid = threadIdx.x;
    {
        const float4* s4 = (const float4*)gW;
        float4* d4 = (float4*)sW;
        for (int i = tid; i < 1920; i += 128) d4[i] = s4[i];
    }
    if (tid < 64) sK[tid] = gK[tid];
    if (tid < 32)       sB[tid] = b_fi[tid];
    else if (tid < 64)  sB[tid] = b_fs[tid - 32];
    else if (tid < 84)  sB[tid] = gBAB[tid - 64];
    __syncthreads();

    const int b0 = blockIdx.x * 256 + tid;
    const int b1 = b0 + 128;

    float2 xr0[16], xr1[16];
    {
        const float4* xp0 = (const float4*)(x + (size_t)b0 * 32);
        const float4* xp1 = (const float4*)(x + (size_t)b1 * 32);
#pragma unroll
        for (int q = 0; q < 8; q++) {
            float4 v0 = xp0[q];
            xr0[2 * q]     = make_float2(v0.x, v0.y);
            xr0[2 * q + 1] = make_float2(v0.z, v0.w);
            float4 v1 = xp1[q];
            xr1[2 * q]     = make_float2(v1.x, v1.y);
            xr1[2 * q + 1] = make_float2(v1.z, v1.w);
        }
    }

    float2 fi0[16], fi1[16], fs0[16], fs1[16], lc0[10], lc1[10];
#pragma unroll
    for (int q = 0; q < 16; q++) {
        float2 bf = make_float2(sB[2 * q],      sB[2 * q + 1]);
        float2 bs = make_float2(sB[32 + 2 * q], sB[32 + 2 * q + 1]);
        fi0[q] = bf; fi1[q] = bf;
        fs0[q] = bs; fs1[q] = bs;
    }
#pragma unroll
    for (int q = 0; q < 10; q++) {
        float2 bl = make_float2(sB[64 + 2 * q], sB[64 + 2 * q + 1]);
        lc0[q] = bl; lc1[q] = bl;
    }

    for (int j = 0; j < 64; j++) {
        const float* wrow = sW + j * 120;
        const float4* wp = (const float4*)wrow;
        float2 a00 = make_float2(0.f, 0.f), a01 = a00;
        float2 a10 = a00, a11 = a00;
#pragma unroll
        for (int q = 0; q < 8; q += 2) {
            float4 w0 = wp[q];
            float4 w1 = wp[q + 1];
            float2 wA = make_float2(w0.x, w0.y);
            float2 wB = make_float2(w0.z, w0.w);
            float2 wC = make_float2(w1.x, w1.y);
            float2 wD = make_float2(w1.z, w1.w);
            a00 = f2fma(xr0[2 * q],     wA, a00);
            a01 = f2fma(xr0[2 * q + 1], wB, a01);
            a10 = f2fma(xr1[2 * q],     wA, a10);
            a11 = f2fma(xr1[2 * q + 1], wB, a11);
            a00 = f2fma(xr0[2 * q + 2], wC, a00);
            a01 = f2fma(xr0[2 * q + 3], wD, a01);
            a10 = f2fma(xr1[2 * q + 2], wC, a10);
            a11 = f2fma(xr1[2 * q + 3], wD, a11);
        }
        float2 p0 = f2add(a00, a01);
        float2 p1 = f2add(a10, a11);
        float kj = sK[j];
        float h0 = p0.x + p0.y + kj;
        float h1 = p1.x + p1.y + kj;

        float ge0 = gelu_fast(h0);
        float ge1 = gelu_fast(h1);
        float2 g0 = make_float2(ge0, ge0);
        float2 g1 = make_float2(ge1, ge1);

        const float4* wi = (const float4*)(wrow + 32);
#pragma unroll
        for (int q = 0; q < 8; q++) {
            float4 a = wi[q];
            float2 wA = make_float2(a.x, a.y);
            float2 wB = make_float2(a.z, a.w);
            fi0[2 * q]     = f2fma(g0, wA, fi0[2 * q]);
            fi0[2 * q + 1] = f2fma(g0, wB, fi0[2 * q + 1]);
            fi1[2 * q]     = f2fma(g1, wA, fi1[2 * q]);
            fi1[2 * q + 1] = f2fma(g1, wB, fi1[2 * q + 1]);
        }
        const float4* wsp = (const float4*)(wrow + 64);
#pragma unroll
        for (int q = 0; q < 8; q++) {
            float4 a = wsp[q];
            float2 wA = make_float2(a.x, a.y);
            float2 wB = make_float2(a.z, a.w);
            fs0[2 * q]     = f2fma(g0, wA, fs0[2 * q]);
            fs0[2 * q + 1] = f2fma(g0, wB, fs0[2 * q + 1]);
            fs1[2 * q]     = f2fma(g1, wA, fs1[2 * q]);
            fs1[2 * q + 1] = f2fma(g1, wB, fs1[2 * q + 1]);
        }
        const float4* wl = (const float4*)(wrow + 96);
#pragma unroll
        for (int q = 0; q < 5; q++) {
            float4 a = wl[q];
            float2 wA = make_float2(a.x, a.y);
            float2 wB = make_float2(a.z, a.w);
            lc0[2 * q]     = f2fma(g0, wA, lc0[2 * q]);
            lc0[2 * q + 1] = f2fma(g0, wB, lc0[2 * q + 1]);
            lc1[2 * q]     = f2fma(g1, wA, lc1[2 * q]);
            lc1[2 * q + 1] = f2fma(g1, wB, lc1[2 * q + 1]);
        }
    }

#pragma unroll
    for (int s = 0; s < 2; s++) {
        float2* fi = s ? fi1 : fi0;
        float2* fs = s ? fs1 : fs0;
        float2* lc = s ? lc1 : lc0;
        float2* xr = s ? xr1 : xr0;
        int b = s ? b1 : b0;

        float m = fmaxf(fi[0].x, fi[0].y);
#pragma unroll
        for (int q = 1; q < 16; q++) m = fmaxf(m, fmaxf(fi[q].x, fi[q].y));
        float S = 0.0f, T = 0.0f;
#pragma unroll
        for (int q = 0; q < 16; q++) {
            float e0 = __expf(fi[q].x - m);
            float e1 = __expf(fi[q].y - m);
            S += e0 + e1;
            T = fmaf(e0, xr[q].x - fs[q].x, T);
            T = fmaf(e1, xr[q].y - fs[q].y, T);
        }
        float sg = 1.0f / (1.0f + __expf(-(T / S)));
        float sA = sg * sg;
        float sC = sg - sA;

        float2* op = (float2*)(out + (size_t)b * 10);
#pragma unroll
        for (int q = 0; q < 5; q++) {
            float2 A  = lc[q];
            float2 Bv = lc[5 + q];
            float2 o;
            o.x = fmaf(sA, A.x, sC * Bv.x);
            o.y = fmaf(sA, A.y, sC * Bv.y);
            op[q] = o;
        }
    }
}

// ---------------- launch ----------------
extern "C" void kernel_launch(void* const* d_in, const int* in_sizes, int n_in,
                              void* d_out, int out_size) {
    const float* x    = (const float*)d_in[0];
    const float* w_in = (const float*)d_in[1];
    const float* b_in = (const float*)d_in[2];
    const float* bn_g = (const float*)d_in[3];
    const float* bn_b = (const float*)d_in[4];
    const float* w_fi = (const float*)d_in[5];
    const float* b_fi = (const float*)d_in[6];
    const float* w_fs = (const float*)d_in[7];
    const float* b_fs = (const float*)d_in[8];
    const float* w_lc = (const float*)d_in[9];
    const float* b_lc = (const float*)d_in[10];
    float* out = (float*)d_out;

    stats_prep_kernel<<<SBLOCKS, 256>>>(x, w_in, b_in, bn_g, bn_b,
                                        w_fi, w_fs, w_lc, b_lc);
    main_kernel<<<B_SAMPLES / 256, 128>>>(x, b_fi, b_fs, out);
}

// round 17
// speedup vs baseline: 1.2103x; 1.2103x over previous
#include <cuda_runtime.h>
#include <math.h>

#define B_SAMPLES 524288
#define SBLOCKS   296
#define NWARPS    (SBLOCKS * 8)         // 2368 warps
#define CHUNKS    (B_SAMPLES / 16)      // 32768 chunks of 16 samples
#define FPSCALE   16777216.0            // 2^24 fixed-point scale

// ---------------- device scratch (static, no allocation) ----------------
__device__ unsigned long long gAcc[1056];      // zero-init; deterministic int accumulation
__device__ int   gTicket;                      // zero-init; self-resetting
__device__ __align__(16) float gW[64 * 120];   // fused per-j row: Wp|fiT|fsT|WAB (+pad)
__device__ float gK[64];
__device__ float gBAB[20];

// ---------------- packed f32x2 helpers ----------------
__device__ __forceinline__ float2 f2fma(float2 a, float2 b, float2 c) {
    float2 d;
    asm("fma.rn.f32x2 %0, %1, %2, %3;"
        : "=l"(reinterpret_cast<unsigned long long&>(d))
        : "l"(reinterpret_cast<const unsigned long long&>(a)),
          "l"(reinterpret_cast<const unsigned long long&>(b)),
          "l"(reinterpret_cast<const unsigned long long&>(c)));
    return d;
}
__device__ __forceinline__ float2 f2add(float2 a, float2 b) {
    float2 d;
    asm("add.rn.f32x2 %0, %1, %2;"
        : "=l"(reinterpret_cast<unsigned long long&>(d))
        : "l"(reinterpret_cast<const unsigned long long&>(a)),
          "l"(reinterpret_cast<const unsigned long long&>(b)));
    return d;
}

// exact-enough GELU: erf via Abramowitz-Stegun 7.1.26 (|eps| <= 1.5e-7 abs)
__device__ __forceinline__ float gelu_fast(float h) {
    float z  = h * 0.70710678118654752f;
    float az = fabsf(z);
    float t  = __fdividef(1.0f, fmaf(0.3275911f, az, 1.0f));
    float p  = t * fmaf(t, fmaf(t, fmaf(t, fmaf(t, 1.061405429f, -1.453152027f),
                                        1.421413741f), -0.284496736f), 0.254829592f);
    float er = 1.0f - p * __expf(-az * az);
    er = copysignf(er, z);
    return 0.5f * h * (1.0f + er);
}

// ---------------- pass 1 (fused): Gram + colsum + int64 reduce + BN-fold/prep ----------------
__global__ void __launch_bounds__(256)
stats_prep_kernel(const float* __restrict__ x,
                  const float* __restrict__ w_in, const float* __restrict__ b_in,
                  const float* __restrict__ bn_g, const float* __restrict__ bn_b,
                  const float* __restrict__ w_fi, const float* __restrict__ w_fs,
                  const float* __restrict__ w_lc, const float* __restrict__ b_lc) {
    __shared__ float pool[8 * 1056];
    __shared__ int   sIsLast;

    const int tid  = threadIdx.x;
    const int lane = tid & 31;
    const int wid  = tid >> 5;
    const int gw   = blockIdx.x * 8 + wid;
    const int ti   = lane >> 2;
    const int tj   = lane & 3;

    float2 acc[4][4];
#pragma unroll
    for (int a = 0; a < 4; a++) {
#pragma unroll
        for (int c = 0; c < 4; c++) acc[a][c] = make_float2(0.f, 0.f);
    }
    float2 cs[4];
#pragma unroll
    for (int c = 0; c < 4; c++) cs[c] = make_float2(0.f, 0.f);

    float* stage = pool + wid * 512;

    for (int ch = gw; ch < CHUNKS; ch += NWARPS) {
        const float4* src = (const float4*)(x + (size_t)ch * 512);
        float4* dst = (float4*)stage;
#pragma unroll
        for (int k = 0; k < 4; k++)
            dst[k * 32 + lane] = src[k * 32 + lane];
        __syncwarp();

#pragma unroll 4
        for (int s = 0; s < 16; s++) {
            const float* row = stage + s * 32;
            float4 xi  = *(const float4*)(row + ti * 4);
            float4 xjA = *(const float4*)(row + tj * 8);
            float4 xjB = *(const float4*)(row + tj * 8 + 4);
            float2 xj[4];
            xj[0] = make_float2(xjA.x, xjA.y);
            xj[1] = make_float2(xjA.z, xjA.w);
            xj[2] = make_float2(xjB.x, xjB.y);
            xj[3] = make_float2(xjB.z, xjB.w);
            float xia[4] = {xi.x, xi.y, xi.z, xi.w};
#pragma unroll
            for (int a = 0; a < 4; a++) {
                float2 f = make_float2(xia[a], xia[a]);
#pragma unroll
                for (int c = 0; c < 4; c++)
                    acc[a][c] = f2fma(f, xj[c], acc[a][c]);
            }
            if (ti == 0) {
#pragma unroll
                for (int c = 0; c < 4; c++) cs[c] = f2add(cs[c], xj[c]);
            }
        }
        __syncwarp();
    }

    __syncthreads();

    float* pw = pool + wid * 1056;
#pragma unroll
    for (int a = 0; a < 4; a++) {
        int r = 4 * ti + a;
#pragma unroll
        for (int c = 0; c < 4; c++) {
            int col = 8 * tj + 2 * c;
            pw[r * 32 + col]     = acc[a][c].x;
            pw[r * 32 + col + 1] = acc[a][c].y;
        }
    }
    if (ti == 0) {
#pragma unroll
        for (int c = 0; c < 4; c++) {
            pw[1024 + 8 * tj + 2 * c]     = cs[c].x;
            pw[1024 + 8 * tj + 2 * c + 1] = cs[c].y;
        }
    }
    __syncthreads();

    // block partial -> deterministic fixed-point accumulation (integer adds commute)
    for (int e = tid; e < 1056; e += 256) {
        float s = 0.0f;
#pragma unroll
        for (int w = 0; w < 8; w++) s += pool[w * 1056 + e];
        long long q = __double2ll_rn((double)s * FPSCALE);
        atomicAdd(&gAcc[e], (unsigned long long)q);
    }

    // ---- last-block finalization ----
    __threadfence();
    __syncthreads();
    if (tid == 0) {
        int t = atomicAdd(&gTicket, 1);
        sIsLast = (t == SBLOCKS - 1) ? 1 : 0;
    }
    __syncthreads();
    if (!sIsLast) return;

    // tiny tail: 1056 loads, convert back, reset for next graph replay
    for (int e = tid; e < 1056; e += 256) {
        long long q = (long long)gAcc[e];
        pool[e] = (float)((double)q * (1.0 / FPSCALE));
        gAcc[e] = 0ULL;
    }
    __syncthreads();
    if (tid == 0) gTicket = 0;

    const int j = tid;
    if (j < 64) {
        float w[32];
#pragma unroll
        for (int f = 0; f < 32; f++) w[f] = w_in[j * 32 + f];

        float s1 = 0.0f;
#pragma unroll
        for (int f = 0; f < 32; f++) s1 = fmaf(w[f], pool[1024 + f], s1);

        float q = 0.0f;
        for (int i = 0; i < 32; i++) {
            float t2 = 0.0f;
#pragma unroll
            for (int f = 0; f < 32; f++) t2 = fmaf(pool[i * 32 + f], w[f], t2);
            q = fmaf(w[i], t2, q);
        }

        const float invB = 1.0f / (float)B_SAMPLES;
        float bj  = b_in[j];
        float mu  = s1 * invB + bj;
        float ex2 = q * invB + 2.0f * bj * (s1 * invB) + bj * bj;
        float var = ex2 - mu * mu;
        float g   = bn_g[j] / sqrtf(var + 1e-5f);
        float k   = g * (bj - mu) + bn_b[j];

        float* row = gW + j * 120;
#pragma unroll
        for (int f = 0; f < 32; f++) row[f] = w[f] * g;
        gK[j] = k;
#pragma unroll
        for (int f = 0; f < 32; f++) {
            row[32 + f] = w_fi[f * 64 + j];
            row[64 + f] = w_fs[f * 64 + j];
        }
#pragma unroll
        for (int c = 0; c < 10; c++) {
            row[96 + c]      = w_lc[c * 64 + j]        + w_lc[(10 + c) * 64 + j];
            row[96 + 10 + c] = w_lc[(20 + c) * 64 + j] + w_lc[(30 + c) * 64 + j];
        }
        row[116] = 0.0f; row[117] = 0.0f; row[118] = 0.0f; row[119] = 0.0f;
        if (j < 10) {
            gBAB[j]      = b_lc[j]      + b_lc[10 + j];
            gBAB[10 + j] = b_lc[20 + j] + b_lc[30 + j];
        }
    }
}

// ---------------- pass 2: main fused kernel (R12 loop body, frozen) ----------------
__global__ void __launch_bounds__(128, 2)
main_kernel(const float* __restrict__ x, const float* __restrict__ b_fi,
            const float* __restrict__ b_fs, float* __restrict__ out) {
    __shared__ __align__(16) float sW[64 * 120];
    __shared__ float sK[64];
    __shared__ float sB[84];

    const int tid = threadIdx.x;
    {
        const float4* s4 = (const float4*)gW;
        float4* d4 = (float4*)sW;
        for (int i = tid; i < 1920; i += 128) d4[i] = s4[i];
    }
    if (tid < 64) sK[tid] = gK[tid];
    if (tid < 32)       sB[tid] = b_fi[tid];
    else if (tid < 64)  sB[tid] = b_fs[tid - 32];
    else if (tid < 84)  sB[tid] = gBAB[tid - 64];
    __syncthreads();

    const int b0 = blockIdx.x * 256 + tid;
    const int b1 = b0 + 128;

    float2 xr0[16], xr1[16];
    {
        const float4* xp0 = (const float4*)(x + (size_t)b0 * 32);
        const float4* xp1 = (const float4*)(x + (size_t)b1 * 32);
#pragma unroll
        for (int q = 0; q < 8; q++) {
            float4 v0 = xp0[q];
            xr0[2 * q]     = make_float2(v0.x, v0.y);
            xr0[2 * q + 1] = make_float2(v0.z, v0.w);
            float4 v1 = xp1[q];
            xr1[2 * q]     = make_float2(v1.x, v1.y);
            xr1[2 * q + 1] = make_float2(v1.z, v1.w);
        }
    }

    float2 fi0[16], fi1[16], fs0[16], fs1[16], lc0[10], lc1[10];
#pragma unroll
    for (int q = 0; q < 16; q++) {
        float2 bf = make_float2(sB[2 * q],      sB[2 * q + 1]);
        float2 bs = make_float2(sB[32 + 2 * q], sB[32 + 2 * q + 1]);
        fi0[q] = bf; fi1[q] = bf;
        fs0[q] = bs; fs1[q] = bs;
    }
#pragma unroll
    for (int q = 0; q < 10; q++) {
        float2 bl = make_float2(sB[64 + 2 * q], sB[64 + 2 * q + 1]);
        lc0[q] = bl; lc1[q] = bl;
    }

    for (int j = 0; j < 64; j++) {
        const float* wrow = sW + j * 120;
        const float4* wp = (const float4*)wrow;
        float2 a00 = make_float2(0.f, 0.f), a01 = a00;
        float2 a10 = a00, a11 = a00;
#pragma unroll
        for (int q = 0; q < 8; q += 2) {
            float4 w0 = wp[q];
            float4 w1 = wp[q + 1];
            float2 wA = make_float2(w0.x, w0.y);
            float2 wB = make_float2(w0.z, w0.w);
            float2 wC = make_float2(w1.x, w1.y);
            float2 wD = make_float2(w1.z, w1.w);
            a00 = f2fma(xr0[2 * q],     wA, a00);
            a01 = f2fma(xr0[2 * q + 1], wB, a01);
            a10 = f2fma(xr1[2 * q],     wA, a10);
            a11 = f2fma(xr1[2 * q + 1], wB, a11);
            a00 = f2fma(xr0[2 * q + 2], wC, a00);
            a01 = f2fma(xr0[2 * q + 3], wD, a01);
            a10 = f2fma(xr1[2 * q + 2], wC, a10);
            a11 = f2fma(xr1[2 * q + 3], wD, a11);
        }
        float2 p0 = f2add(a00, a01);
        float2 p1 = f2add(a10, a11);
        float kj = sK[j];
        float h0 = p0.x + p0.y + kj;
        float h1 = p1.x + p1.y + kj;

        float ge0 = gelu_fast(h0);
        float ge1 = gelu_fast(h1);
        float2 g0 = make_float2(ge0, ge0);
        float2 g1 = make_float2(ge1, ge1);

        const float4* wi = (const float4*)(wrow + 32);
#pragma unroll
        for (int q = 0; q < 8; q++) {
            float4 a = wi[q];
            float2 wA = make_float2(a.x, a.y);
            float2 wB = make_float2(a.z, a.w);
            fi0[2 * q]     = f2fma(g0, wA, fi0[2 * q]);
            fi0[2 * q + 1] = f2fma(g0, wB, fi0[2 * q + 1]);
            fi1[2 * q]     = f2fma(g1, wA, fi1[2 * q]);
            fi1[2 * q + 1] = f2fma(g1, wB, fi1[2 * q + 1]);
        }
        const float4* wsp = (const float4*)(wrow + 64);
#pragma unroll
        for (int q = 0; q < 8; q++) {
            float4 a = wsp[q];
            float2 wA = make_float2(a.x, a.y);
            float2 wB = make_float2(a.z, a.w);
            fs0[2 * q]     = f2fma(g0, wA, fs0[2 * q]);
            fs0[2 * q + 1] = f2fma(g0, wB, fs0[2 * q + 1]);
            fs1[2 * q]     = f2fma(g1, wA, fs1[2 * q]);
            fs1[2 * q + 1] = f2fma(g1, wB, fs1[2 * q + 1]);
        }
        const float4* wl = (const float4*)(wrow + 96);
#pragma unroll
        for (int q = 0; q < 5; q++) {
            float4 a = wl[q];
            float2 wA = make_float2(a.x, a.y);
            float2 wB = make_float2(a.z, a.w);
            lc0[2 * q]     = f2fma(g0, wA, lc0[2 * q]);
            lc0[2 * q + 1] = f2fma(g0, wB, lc0[2 * q + 1]);
            lc1[2 * q]     = f2fma(g1, wA, lc1[2 * q]);
            lc1[2 * q + 1] = f2fma(g1, wB, lc1[2 * q + 1]);
        }
    }

#pragma unroll
    for (int s = 0; s < 2; s++) {
        float2* fi = s ? fi1 : fi0;
        float2* fs = s ? fs1 : fs0;
        float2* lc = s ? lc1 : lc0;
        float2* xr = s ? xr1 : xr0;
        int b = s ? b1 : b0;

        float m = fmaxf(fi[0].x, fi[0].y);
#pragma unroll
        for (int q = 1; q < 16; q++) m = fmaxf(m, fmaxf(fi[q].x, fi[q].y));
        float S = 0.0f, T = 0.0f;
#pragma unroll
        for (int q = 0; q < 16; q++) {
            float e0 = __expf(fi[q].x - m);
            float e1 = __expf(fi[q].y - m);
            S += e0 + e1;
            T = fmaf(e0, xr[q].x - fs[q].x, T);
            T = fmaf(e1, xr[q].y - fs[q].y, T);
        }
        float sg = 1.0f / (1.0f + __expf(-(T / S)));
        float sA = sg * sg;
        float sC = sg - sA;

        float2* op = (float2*)(out + (size_t)b * 10);
#pragma unroll
        for (int q = 0; q < 5; q++) {
            float2 A  = lc[q];
            float2 Bv = lc[5 + q];
            float2 o;
            o.x = fmaf(sA, A.x, sC * Bv.x);
            o.y = fmaf(sA, A.y, sC * Bv.y);
            op[q] = o;
        }
    }
}

// ---------------- launch ----------------
extern "C" void kernel_launch(void* const* d_in, const int* in_sizes, int n_in,
                              void* d_out, int out_size) {
    const float* x    = (const float*)d_in[0];
    const float* w_in = (const float*)d_in[1];
    const float* b_in = (const float*)d_in[2];
    const float* bn_g = (const float*)d_in[3];
    const float* bn_b = (const float*)d_in[4];
    const float* w_fi = (const float*)d_in[5];
    const float* b_fi = (const float*)d_in[6];
    const float* w_fs = (const float*)d_in[7];
    const float* b_fs = (const float*)d_in[8];
    const float* w_lc = (const float*)d_in[9];
    const float* b_lc = (const float*)d_in[10];
    float* out = (float*)d_out;

    stats_prep_kernel<<<SBLOCKS, 256>>>(x, w_in, b_in, bn_g, bn_b,
                                        w_fi, w_fs, w_lc, b_lc);
    main_kernel<<<B_SAMPLES / 256, 128>>>(x, b_fi, b_fs, out);
}